// round 17
// baseline (speedup 1.0000x reference)
#include <cuda_runtime.h>
#include <cuda_fp16.h>
#include <math.h>
#include <stdint.h>

#define BB 2
#define HH 16
#define NSEQ 2048
#define DD 64
#define CC 1024
#define MM (BB*NSEQ)      /* 4096 */
#define K3 (3*CC)         /* 3072 */

// ---------------------------------------------------------------------------
// Scratch (__device__ globals; allocation-free rule)
// ---------------------------------------------------------------------------
__device__ __align__(256) __half g_qh[(size_t)BB*HH*NSEQ*DD];   // Q fp16, pre-scaled 0.125*log2e
__device__ __align__(256) __half g_kh[(size_t)BB*HH*NSEQ*DD];
__device__ __align__(256) __half g_vh[(size_t)BB*HH*NSEQ*DD];
__device__ __align__(256) __half g_xh[(size_t)MM*CC];           // x cast to fp16
__device__ __align__(256) __half g_Oh[(size_t)MM*CC];           // attention out, fp16
__device__ __align__(256) __half g_Bq[(size_t)K3*CC];           // W_qkv fp16 K-major
__device__ __align__(256) __half g_Bo[(size_t)CC*CC];           // W_out fp16 K-major

// ---------------------------------------------------------------------------
// PTX helpers
// ---------------------------------------------------------------------------
__device__ __forceinline__ uint32_t smem_u32(const void* p) {
    uint32_t a;
    asm("{ .reg .u64 t; cvta.to.shared.u64 t, %1; cvt.u32.u64 %0, t; }"
        : "=r"(a) : "l"(p));
    return a;
}

#define SW128(off) ((off) ^ (((off) >> 3) & 0x70))

#define CP16(dst, src) \
    asm volatile("cp.async.cg.shared.global [%0], [%1], 16;" :: "r"(dst), "l"(src))
#define CP_COMMIT() asm volatile("cp.async.commit_group;" ::: "memory")
#define CP_WAIT1()  asm volatile("cp.async.wait_group 1;" ::: "memory")

__device__ __forceinline__ void grid_dep_sync() {
#if defined(__CUDA_ARCH__) && __CUDA_ARCH__ >= 900
    cudaGridDependencySynchronize();
#endif
}

__device__ __forceinline__ void ldsm4(uint32_t& r0, uint32_t& r1,
                                      uint32_t& r2, uint32_t& r3, uint32_t a) {
    asm volatile("ldmatrix.sync.aligned.m8n8.x4.shared.b16 {%0,%1,%2,%3}, [%4];"
        : "=r"(r0), "=r"(r1), "=r"(r2), "=r"(r3) : "r"(a));
}
__device__ __forceinline__ void ldsm4t(uint32_t& r0, uint32_t& r1,
                                       uint32_t& r2, uint32_t& r3, uint32_t a) {
    asm volatile("ldmatrix.sync.aligned.m8n8.x4.trans.shared.b16 {%0,%1,%2,%3}, [%4];"
        : "=r"(r0), "=r"(r1), "=r"(r2), "=r"(r3) : "r"(a));
}
__device__ __forceinline__ void mma_f16(float* c, const uint32_t* a, uint32_t b0, uint32_t b1) {
    asm volatile("mma.sync.aligned.m16n8k16.row.col.f32.f16.f16.f32 "
        "{%0,%1,%2,%3}, {%4,%5,%6,%7}, {%8,%9}, {%0,%1,%2,%3};"
        : "+f"(c[0]), "+f"(c[1]), "+f"(c[2]), "+f"(c[3])
        : "r"(a[0]), "r"(a[1]), "r"(a[2]), "r"(a[3]), "r"(b0), "r"(b1));
}

__device__ __forceinline__ uint32_t pack_h2(float lo, float hi) {
    __half2 h = __float22half2_rn(make_float2(lo, hi));
    return *(uint32_t*)&h;
}
__device__ __forceinline__ uint32_t ex2_h2(uint32_t x) {
    uint32_t r;
    asm("ex2.approx.f16x2 %0, %1;" : "=r"(r) : "r"(x));
    return r;
}
__device__ __forceinline__ float ex2_f32(float x) {
    float r;
    asm("ex2.approx.f32 %0, %1;" : "=f"(r) : "f"(x));
    return r;
}

// ---------------------------------------------------------------------------
// Prep W: transpose+cast both weight matrices (K-major), uint2 stores.
// ---------------------------------------------------------------------------
#define NB_TQ ((CC / 32) * (K3 / 32))   /* 3072 */
#define NB_TO ((CC / 32) * (CC / 32))   /* 1024 */

__global__ __launch_bounds__(256) void prepW_kernel(
    const float* __restrict__ Wq, const float* __restrict__ Wo,
    __half* __restrict__ Bq, __half* __restrict__ Bo)
{
    const int bid = blockIdx.x, tid = threadIdx.x;
    const float* W; __half* Bd; int N, b;
    if (bid < NB_TQ) { b = bid;         W = Wq; Bd = Bq; N = K3; }
    else             { b = bid - NB_TQ; W = Wo; Bd = Bo; N = CC; }
    const int k0 = (b % 32) * 32;
    const int n0 = (b / 32) * 32;
    const int tx = tid & 31, ty = tid >> 5;

    __shared__ float t[32][33];
    #pragma unroll
    for (int i = 0; i < 4; i++)
        t[ty + i * 8][tx] = W[(size_t)(k0 + ty + i * 8) * N + n0 + tx];
    __syncthreads();

    const int n = tid >> 3;
    const int g = (tid & 7) * 4;
    __half2 p0 = __float22half2_rn(make_float2(t[g + 0][n], t[g + 1][n]));
    __half2 p1 = __float22half2_rn(make_float2(t[g + 2][n], t[g + 3][n]));
    *(uint2*)&Bd[(size_t)(n0 + n) * CC + k0 + g] =
        make_uint2(*(uint32_t*)&p0, *(uint32_t*)&p1);
}

// ---------------------------------------------------------------------------
// Prep X: cast x->fp16, 8 elems/thread.
// ---------------------------------------------------------------------------
#define NB_CAST (MM * CC / 2048)        /* 2048 */

__global__ __launch_bounds__(256) void prepX_kernel(
    const float* __restrict__ x, __half* __restrict__ xh)
{
    size_t idx8 = ((size_t)blockIdx.x * 256 + threadIdx.x) * 8;
    float4 v0 = *(const float4*)&x[idx8];
    float4 v1 = *(const float4*)&x[idx8 + 4];
    __half2 a = __float22half2_rn(make_float2(v0.x, v0.y));
    __half2 b = __float22half2_rn(make_float2(v0.z, v0.w));
    __half2 c = __float22half2_rn(make_float2(v1.x, v1.y));
    __half2 d = __float22half2_rn(make_float2(v1.z, v1.w));
    *(uint4*)&xh[idx8] = make_uint4(*(uint32_t*)&a, *(uint32_t*)&b,
                                    *(uint32_t*)&c, *(uint32_t*)&d);
}

// ---------------------------------------------------------------------------
// HMMA GEMM: D[M][N] = A[M][1024] @ B[N][1024]^T (+bias)
// BM=128, BN=128, BK=64, 3-stage cp.async, 1 sync/iter, 2 CTAs/SM.
// PDL: B (weights, ready upstream) prefetched for stages 0/1 BEFORE the
// grid-dependency sync; A loads after. Group accounting: G0={B0,B1,A0},
// G1={A1}; wait_group(1) at iter 0 drains G0 (covers buf0), at iter 1 drains
// G1 too (A1; B1 already in G0).
// ---------------------------------------------------------------------------
#define STAGE_BYTES 32768
#define GEMM_SMEM (3 * STAGE_BYTES + 128)
#define KEXT 1024
#define KITERS (KEXT / 64)
#define QSCALE 0.18033688f   /* 0.125 * log2(e) */

template<int MODE>
__global__ __launch_bounds__(256, 2) void mma_gemm_kernel(
    const __half* __restrict__ A,
    const __half* __restrict__ Bm,
    const float* __restrict__ bias,
    float* __restrict__ Cout,
    __half* __restrict__ Qh, __half* __restrict__ Kh, __half* __restrict__ Vh)
{
    extern __shared__ char smraw[];
    char* smp = (char*)(((uintptr_t)smraw + 127) & ~(uintptr_t)127);
    const uint32_t sb = smem_u32(smp);

    const int tid = threadIdx.x;
    const int lane = tid & 31, wid = tid >> 5;
    const int wm = wid & 3, wn = wid >> 2;
    const int m0 = blockIdx.y * 128;
    const int n0 = blockIdx.x * 128;

    const char* gA = (const char*)A + (size_t)m0 * (KEXT * 2);
    const char* gB = (const char*)Bm + (size_t)n0 * (KEXT * 2);

    const int crow = tid >> 3;
    const int ccol = (tid & 7) * 16;

    auto load_A = [&](int it, int buf) {
        const uint32_t ao = (uint32_t)buf * STAGE_BYTES;
        const size_t kbyte = (size_t)it * 128;
        #pragma unroll
        for (int i = 0; i < 4; i++) {
            int r = crow + i * 32;
            CP16(sb + ao + SW128(r * 128 + ccol),
                 gA + (size_t)r * (KEXT * 2) + kbyte + ccol);
        }
    };
    auto load_B = [&](int it, int buf) {
        const uint32_t bo = (uint32_t)buf * STAGE_BYTES + 16384u;
        const size_t kbyte = (size_t)it * 128;
        #pragma unroll
        for (int i = 0; i < 4; i++) {
            int r = crow + i * 32;
            CP16(sb + bo + SW128(r * 128 + ccol),
                 gB + (size_t)r * (KEXT * 2) + kbyte + ccol);
        }
    };
    auto load_tile = [&](int it, int buf) { load_A(it, buf); load_B(it, buf); };

    float acc[2][8][4];
    #pragma unroll
    for (int mt = 0; mt < 2; mt++)
        #pragma unroll
        for (int nt = 0; nt < 8; nt++)
            #pragma unroll
            for (int j = 0; j < 4; j++) acc[mt][nt][j] = 0.f;

    // PDL prologue: B operand is weights (ready before this kernel's primary
    // even started). Prefetch B stages 0/1 into the primary's tail window.
    load_B(0, 0);
    load_B(1, 1);
    grid_dep_sync();
    load_A(0, 0); CP_COMMIT();      // G0 = {B0, B1, A0}
    load_A(1, 1); CP_COMMIT();      // G1 = {A1}

    int buf = 0;
    for (int it = 0; it < KITERS; it++) {
        CP_WAIT1();
        __syncthreads();
        if (it + 2 < KITERS) load_tile(it + 2, (buf + 2) % 3);
        CP_COMMIT();

        const uint32_t ao = (uint32_t)buf * STAGE_BYTES;
        const uint32_t bo = ao + 16384u;

        #pragma unroll
        for (int ks = 0; ks < 4; ks++) {
            uint32_t a[2][4];
            #pragma unroll
            for (int mt = 0; mt < 2; mt++) {
                uint32_t addr = sb + ao +
                    SW128((wm * 32 + mt * 16 + (lane & 15)) * 128 +
                          ks * 32 + ((lane >> 4) << 4));
                ldsm4(a[mt][0], a[mt][1], a[mt][2], a[mt][3], addr);
            }
            uint32_t b[8][2];
            #pragma unroll
            for (int p = 0; p < 4; p++) {
                uint32_t addr = sb + bo +
                    SW128((wn * 64 + p * 16 + (lane & 7) + ((lane >> 4) & 1) * 8) * 128 +
                          ks * 32 + ((lane >> 3) & 1) * 16);
                ldsm4(b[2 * p][0], b[2 * p][1], b[2 * p + 1][0], b[2 * p + 1][1], addr);
            }
            #pragma unroll
            for (int mt = 0; mt < 2; mt++)
                #pragma unroll
                for (int nt = 0; nt < 8; nt++)
                    mma_f16(acc[mt][nt], a[mt], b[nt][0], b[nt][1]);
        }
        buf = (buf + 1) % 3;
    }

    const int colbase = n0 + wn * 64;
    if (MODE == 0) {
        const int s = colbase >> 10;
        const int h = (colbase >> 6) & 15;
        __half* dst = (s == 0) ? Qh : ((s == 1) ? Kh : Vh);
        const float scl = (s == 0) ? QSCALE : 1.0f;
        #pragma unroll
        for (int mt = 0; mt < 2; mt++) {
            #pragma unroll
            for (int hf = 0; hf < 2; hf++) {
                int r = m0 + wm * 32 + mt * 16 + (lane >> 2) + hf * 8;
                int bidx = r >> 11, n = r & (NSEQ - 1);
                size_t rowoff = (((size_t)bidx * HH + h) * NSEQ + n) * DD;
                #pragma unroll
                for (int nt = 0; nt < 8; nt++) {
                    int dd = nt * 8 + (lane & 3) * 2;
                    float v0 = (acc[mt][nt][hf * 2 + 0] + bias[colbase + dd]) * scl;
                    float v1 = (acc[mt][nt][hf * 2 + 1] + bias[colbase + dd + 1]) * scl;
                    *(__half2*)&dst[rowoff + dd] =
                        __float22half2_rn(make_float2(v0, v1));
                }
            }
        }
    } else {
        #pragma unroll
        for (int mt = 0; mt < 2; mt++) {
            #pragma unroll
            for (int hf = 0; hf < 2; hf++) {
                int r = m0 + wm * 32 + mt * 16 + (lane >> 2) + hf * 8;
                float* crow2 = &Cout[(size_t)r * CC];
                #pragma unroll
                for (int nt = 0; nt < 8; nt++) {
                    int cc = colbase + nt * 8 + (lane & 3) * 2;
                    float2 o;
                    o.x = acc[mt][nt][hf * 2 + 0] + bias[cc];
                    o.y = acc[mt][nt][hf * 2 + 1] + bias[cc + 1];
                    *(float2*)&crow2[cc] = o;
                }
            }
        }
    }
}

// ---------------------------------------------------------------------------
// Flash attention — R15/R16 verbatim + grid_dep_sync at entry (all inputs
// come from the qkv kernel). 6-stage KV ring, barrier every 4 iters,
// fp16 HMMA, log2 softmax, Q hoisted, rowsum via ones-MMA, V via ldsm4t.
// ---------------------------------------------------------------------------
#define FL_SQ 0u
#define FL_KV(buf) (16384u + (uint32_t)(buf) * 16384u)
#define FL_NBUF 6
#define FL_SMEM (16384 + FL_NBUF * 16384 + 128)
#define NKB (NSEQ / 64)
#define ONES2 0x3C003C00u

__global__ __launch_bounds__(256, 2) void flash_mma_kernel(
    const __half* __restrict__ Qh, const __half* __restrict__ Kh,
    const __half* __restrict__ Vh, __half* __restrict__ Oh)
{
    extern __shared__ char smraw[];
    char* smp = (char*)(((uintptr_t)smraw + 127) & ~(uintptr_t)127);
    const uint32_t sb = smem_u32(smp);

    const int tid = threadIdx.x;
    const int lane = tid & 31, w = tid >> 5;
    const int bh = blockIdx.y;
    const int q0 = blockIdx.x * 128;
    const size_t base = (size_t)bh * NSEQ * DD;

    const char* gK = (const char*)(Kh + base);
    const char* gV = (const char*)(Vh + base);
    const int crow = tid >> 3;
    const int ccol = (tid & 7) * 16;

    grid_dep_sync();

    auto load_kv = [&](int kc, int buf) {
        const size_t rb = (size_t)kc * 64 * 128;
        const uint32_t ko = FL_KV(buf), vo = ko + 8192u;
        #pragma unroll
        for (int i = 0; i < 2; i++) {
            int r = crow + i * 32;
            CP16(sb + ko + SW128(r * 128 + ccol), gK + rb + (size_t)r * 128 + ccol);
        }
        #pragma unroll
        for (int i = 0; i < 2; i++) {
            int r = crow + i * 32;
            CP16(sb + vo + SW128(r * 128 + ccol), gV + rb + (size_t)r * 128 + ccol);
        }
    };

    {
        const char* gQ = (const char*)(Qh + base + (size_t)q0 * DD);
        #pragma unroll
        for (int i = 0; i < 4; i++) {
            int r = crow + i * 32;
            CP16(sb + FL_SQ + SW128(r * 128 + ccol), gQ + (size_t)r * 128 + ccol);
        }
    }
    load_kv(0, 0); CP_COMMIT();
    load_kv(1, 1); CP_COMMIT();

    uint32_t qf[4][4];
    float oacc[8][4];
    #pragma unroll
    for (int nt = 0; nt < 8; nt++)
        #pragma unroll
        for (int j = 0; j < 4; j++) oacc[nt][j] = 0.f;
    float m0r = -1e30f, m1r = -1e30f, l0r = 0.f, l1r = 0.f;

    int buf = 0;
    for (int kc = 0; kc < NKB; kc++) {
        CP_WAIT1();
        if ((kc & 3) == 0) __syncthreads();
        if (kc + 2 < NKB) load_kv(kc + 2, (buf + 2) % FL_NBUF);
        CP_COMMIT();

        if (kc == 0) {
            #pragma unroll
            for (int ks = 0; ks < 4; ks++)
                ldsm4(qf[ks][0], qf[ks][1], qf[ks][2], qf[ks][3],
                      sb + FL_SQ + SW128((w * 16 + (lane & 15)) * 128 +
                                         ks * 32 + ((lane >> 4) << 4)));
        }
        const uint32_t ko = FL_KV(buf), vo = ko + 8192u;

        float sacc[8][4];
        #pragma unroll
        for (int nt = 0; nt < 8; nt++)
            #pragma unroll
            for (int j = 0; j < 4; j++) sacc[nt][j] = 0.f;

        #pragma unroll
        for (int ks = 0; ks < 4; ks++) {
            #pragma unroll
            for (int p = 0; p < 4; p++) {
                uint32_t b0, b1, b2, b3;
                ldsm4(b0, b1, b2, b3,
                      sb + ko + SW128((p * 16 + (lane & 7) + ((lane >> 4) & 1) * 8) * 128 +
                                      ks * 32 + ((lane >> 3) & 1) * 16));
                mma_f16(sacc[2 * p], qf[ks], b0, b1);
                mma_f16(sacc[2 * p + 1], qf[ks], b2, b3);
            }
        }

        float mx0 = m0r, mx1 = m1r;
        #pragma unroll
        for (int nt = 0; nt < 8; nt++) {
            mx0 = fmaxf(mx0, fmaxf(sacc[nt][0], sacc[nt][1]));
            mx1 = fmaxf(mx1, fmaxf(sacc[nt][2], sacc[nt][3]));
        }
        mx0 = fmaxf(mx0, __shfl_xor_sync(0xffffffffu, mx0, 1));
        mx0 = fmaxf(mx0, __shfl_xor_sync(0xffffffffu, mx0, 2));
        mx1 = fmaxf(mx1, __shfl_xor_sync(0xffffffffu, mx1, 1));
        mx1 = fmaxf(mx1, __shfl_xor_sync(0xffffffffu, mx1, 2));

        float alpha0 = ex2_f32(m0r - mx0);
        float alpha1 = ex2_f32(m1r - mx1);
        m0r = mx0; m1r = mx1;

        if (__any_sync(0xffffffffu, (alpha0 != 1.f) || (alpha1 != 1.f))) {
            #pragma unroll
            for (int nt = 0; nt < 8; nt++) {
                oacc[nt][0] *= alpha0; oacc[nt][1] *= alpha0;
                oacc[nt][2] *= alpha1; oacc[nt][3] *= alpha1;
            }
        }

        float ssum[4] = {0.f, 0.f, 0.f, 0.f};
        #pragma unroll
        for (int kt = 0; kt < 4; kt++) {
            uint32_t pa[4];
            pa[0] = ex2_h2(pack_h2(sacc[2 * kt][0] - mx0,     sacc[2 * kt][1] - mx0));
            pa[1] = ex2_h2(pack_h2(sacc[2 * kt][2] - mx1,     sacc[2 * kt][3] - mx1));
            pa[2] = ex2_h2(pack_h2(sacc[2 * kt + 1][0] - mx0, sacc[2 * kt + 1][1] - mx0));
            pa[3] = ex2_h2(pack_h2(sacc[2 * kt + 1][2] - mx1, sacc[2 * kt + 1][3] - mx1));
            mma_f16(ssum, pa, ONES2, ONES2);
            #pragma unroll
            for (int ntp = 0; ntp < 4; ntp++) {
                uint32_t v0, v1, v2, v3;
                ldsm4t(v0, v1, v2, v3,
                       sb + vo + SW128((kt * 16 + (lane & 15)) * 128 +
                                       ntp * 32 + ((lane >> 4) << 4)));
                mma_f16(oacc[2 * ntp],     pa, v0, v1);
                mma_f16(oacc[2 * ntp + 1], pa, v2, v3);
            }
        }
        l0r = l0r * alpha0 + ssum[0];
        l1r = l1r * alpha1 + ssum[2];

        buf = (buf + 1) % FL_NBUF;
    }

    const float inv0 = 1.f / l0r, inv1 = 1.f / l1r;
    const int b = bh >> 4, h = bh & 15;
    #pragma unroll
    for (int hf = 0; hf < 2; hf++) {
        int n = q0 + w * 16 + (lane >> 2) + hf * 8;
        float inv = hf ? inv1 : inv0;
        __half* orow = Oh + ((size_t)b * NSEQ + n) * CC;
        #pragma unroll
        for (int nt = 0; nt < 8; nt++) {
            int col = h * 64 + nt * 8 + (lane & 3) * 2;
            float o0 = oacc[nt][hf * 2 + 0] * inv;
            float o1 = oacc[nt][hf * 2 + 1] * inv;
            *(__half2*)&orow[col] = __float22half2_rn(make_float2(o0, o1));
        }
    }
}

// ---------------------------------------------------------------------------
// Launcher — PDL chain: prepW | prepX || qkv [PDL] || flash [PDL] || outproj [PDL]
// ---------------------------------------------------------------------------
static void launch_pdl(const void* func, dim3 grid, dim3 block, size_t smem,
                       void** args)
{
    cudaLaunchConfig_t cfg = {};
    cfg.gridDim = grid;
    cfg.blockDim = block;
    cfg.dynamicSmemBytes = smem;
    cfg.stream = 0;
    cudaLaunchAttribute attr;
    attr.id = cudaLaunchAttributeProgrammaticStreamSerialization;
    attr.val.programmaticStreamSerializationAllowed = 1;
    cfg.attrs = &attr;
    cfg.numAttrs = 1;
    cudaLaunchKernelExC(&cfg, func, args);
}

extern "C" void kernel_launch(void* const* d_in, const int* in_sizes, int n_in,
                              void* d_out, int out_size)
{
    const float* x     = (const float*)d_in[0];
    const float* W_qkv = (const float*)d_in[1];
    const float* b_qkv = (const float*)d_in[2];
    const float* W_out = (const float*)d_in[3];
    const float* b_out = (const float*)d_in[4];
    float* out = (float*)d_out;

    __half *qh, *kh, *vh, *xh, *Oh, *Bq, *Bo;
    cudaGetSymbolAddress((void**)&qh, g_qh);
    cudaGetSymbolAddress((void**)&kh, g_kh);
    cudaGetSymbolAddress((void**)&vh, g_vh);
    cudaGetSymbolAddress((void**)&xh, g_xh);
    cudaGetSymbolAddress((void**)&Oh, g_Oh);
    cudaGetSymbolAddress((void**)&Bq, g_Bq);
    cudaGetSymbolAddress((void**)&Bo, g_Bo);

    cudaFuncSetAttribute((const void*)mma_gemm_kernel<0>,
                         cudaFuncAttributeMaxDynamicSharedMemorySize, GEMM_SMEM);
    cudaFuncSetAttribute((const void*)mma_gemm_kernel<1>,
                         cudaFuncAttributeMaxDynamicSharedMemorySize, GEMM_SMEM);
    cudaFuncSetAttribute(flash_mma_kernel,
                         cudaFuncAttributeMaxDynamicSharedMemorySize, FL_SMEM);

    float* nullf = nullptr;
    __half* nullh = nullptr;

    // 1) weights prep (plain) — must fully precede everything that reads Bq/Bo
    prepW_kernel<<<NB_TQ + NB_TO, 256>>>(W_qkv, W_out, Bq, Bo);
    // 2) x cast (plain; full barrier behind prepW so qkv's pre-sync B reads are safe)
    prepX_kernel<<<NB_CAST, 256>>>(x, xh);
    // 3) qkv projection [PDL: B-prefetch pre-sync]
    {
        void* args[] = {&xh, &Bq, (void*)&b_qkv, &nullf, &qh, &kh, &vh};
        launch_pdl((const void*)mma_gemm_kernel<0>,
                   dim3(K3 / 128, MM / 128), dim3(256), GEMM_SMEM, args);
    }
    // 4) flash attention [PDL: sync at entry]
    {
        void* args[] = {&qh, &kh, &vh, &Oh};
        launch_pdl((const void*)flash_mma_kernel,
                   dim3(NSEQ / 128, BB * HH), dim3(256), FL_SMEM, args);
    }
    // 5) output projection [PDL: B-prefetch pre-sync]
    {
        void* args[] = {&Oh, &Bo, (void*)&b_out, &out, &nullh, &nullh, &nullh};
        launch_pdl((const void*)mma_gemm_kernel<1>,
                   dim3(CC / 128, MM / 128), dim3(256), GEMM_SMEM, args);
    }
}